// round 14
// baseline (speedup 1.0000x reference)
#include <cuda_runtime.h>
#include <cuda_bf16.h>
#include <cstdint>

#define B_ 8
#define L_ 2048
#define V_ 10000
#define H_ 512

static const long long LH = (long long)L_ * H_;       // 1048576
static const long long LL = (long long)L_ * L_;       // 4194304

// ---------------- static device scratch (no allocations) ----------------
__device__ float g_embproj[V_ * H_];                   // 20.5 MB
__device__ float g_z[B_ * L_ * H_];                    // 33.5 MB
__device__ float g_P[(size_t)B_ * L_ * L_];            // 134 MB (raw scores)
__device__ float g_dec[B_ * L_ * H_];                  // 33.5 MB

__device__ __nv_bfloat16 g_P_hi[(size_t)B_ * L_ * L_]; // 67 MB (probs hi)
__device__ __nv_bfloat16 g_P_lo[(size_t)B_ * L_ * L_]; // 67 MB (probs lo)
__device__ __nv_bfloat16 g_zT_hi[B_ * H_ * L_];        // 16.8 MB (z^T)
__device__ __nv_bfloat16 g_zT_lo[B_ * H_ * L_];
__device__ __nv_bfloat16 g_dec_hi[B_ * L_ * H_];
__device__ __nv_bfloat16 g_dec_lo[B_ * L_ * H_];
__device__ __nv_bfloat16 g_wd_hi[V_ * H_];
__device__ __nv_bfloat16 g_wd_lo[V_ * H_];
__device__ __nv_bfloat16 g_z_hi[B_ * L_ * H_];
__device__ __nv_bfloat16 g_z_lo[B_ * L_ * H_];
__device__ __nv_bfloat16 g_av_hi[B_ * L_ * H_];
__device__ __nv_bfloat16 g_av_lo[B_ * L_ * H_];
__device__ __nv_bfloat16 g_emb_hi[V_ * H_];
__device__ __nv_bfloat16 g_emb_lo[V_ * H_];
__device__ __nv_bfloat16 g_wih_hi[H_ * H_];
__device__ __nv_bfloat16 g_wih_lo[H_ * H_];
__device__ __nv_bfloat16 g_wc_hi[H_ * 2 * H_];
__device__ __nv_bfloat16 g_wc_lo[H_ * 2 * H_];

__device__ __forceinline__ uint32_t smem_u32(const void* p) {
    uint32_t a;
    asm("{ .reg .u64 t; cvta.to.shared.u64 t, %1; cvt.u32.u64 %0, t; }"
        : "=r"(a) : "l"(p));
    return a;
}

#define LDSM_X4(r0, r1, r2, r3, addr)                                         \
    asm volatile("ldmatrix.sync.aligned.m8n8.x4.shared.b16 {%0,%1,%2,%3}, [%4];" \
                 : "=r"(r0), "=r"(r1), "=r"(r2), "=r"(r3) : "r"(addr))
#define LDSM_X2(r0, r1, addr)                                                 \
    asm volatile("ldmatrix.sync.aligned.m8n8.x2.shared.b16 {%0,%1}, [%2];"    \
                 : "=r"(r0), "=r"(r1) : "r"(addr))
#define MMA_BF16(c, a, b)                                                     \
    asm volatile("mma.sync.aligned.m16n8k16.row.col.f32.bf16.bf16.f32 "       \
                 "{%0,%1,%2,%3}, {%4,%5,%6,%7}, {%8,%9}, {%0,%1,%2,%3};"      \
                 : "+f"((c)[0]), "+f"((c)[1]), "+f"((c)[2]), "+f"((c)[3])     \
                 : "r"((a)[0]), "r"((a)[1]), "r"((a)[2]), "r"((a)[3]),        \
                   "r"((b)[0]), "r"((b)[1]))

__device__ __forceinline__ void cp16(uint32_t dst, const void* src, bool pred) {
    int sz = pred ? 16 : 0;
    asm volatile("cp.async.cg.shared.global [%0], [%1], 16, %2;"
                 :: "r"(dst), "l"(src), "r"(sz));
}
#define CP_COMMIT() asm volatile("cp.async.commit_group;" ::: "memory")
#define CP_WAIT1()  asm volatile("cp.async.wait_group 1;" ::: "memory")
#define CP_WAIT0()  asm volatile("cp.async.wait_group 0;" ::: "memory")

// ======================================================================
// Generic split-bf16 HMMA NT GEMM (2-stage cp.async, 2 CTAs/SM):
//   C[M,N] = (Ahi+Alo)[M,K] @ (Bhi+Blo)[N,K]^T (+bias) (+=C)
// flags: bit0 = accumulate (reads fp32 C), bit1 = causal tile skip,
//        bit2 = causal K-limit, bit3 = write output as bf16 hi/lo
// ======================================================================
#define HG_STRIDE 40
#define HG_ARR    (128 * HG_STRIDE)              // 5120 bf16 per array
#define HG_STAGE  (4 * HG_ARR)                   // per stage (Ahi,Alo,Bhi,Blo)
#define HG_SMEM   (2 * HG_STAGE * 2)             // 81920 bytes (2 stages)

__global__ __launch_bounds__(256, 2) void hgemm_nt(
    const __nv_bfloat16* __restrict__ Ahi, const __nv_bfloat16* __restrict__ Alo,
    int lda, long long sA,
    const __nv_bfloat16* __restrict__ Bhi, const __nv_bfloat16* __restrict__ Blo,
    int ldb, long long sB,
    float* __restrict__ C,
    __nv_bfloat16* __restrict__ Chi, __nv_bfloat16* __restrict__ Clo,
    int ldc, long long sC,
    int M, int N, int K,
    const float* __restrict__ bias, int flags)
{
    if ((flags & 2) && blockIdx.x > blockIdx.y) return;
    Ahi += (long long)blockIdx.z * sA;  Alo += (long long)blockIdx.z * sA;
    Bhi += (long long)blockIdx.z * sB;  Blo += (long long)blockIdx.z * sB;
    C   += (long long)blockIdx.z * sC;
    if (Chi) { Chi += (long long)blockIdx.z * sC; Clo += (long long)blockIdx.z * sC; }

    extern __shared__ __nv_bfloat16 sm[];
    const uint32_t smem_base = smem_u32(sm);
    const int tid  = threadIdx.x;
    const int wid  = tid >> 5;
    const int lane = tid & 31;
    const int m0 = blockIdx.y * 128;
    const int n0 = blockIdx.x * 128;
    const int wm = wid >> 2;
    const int wn = wid & 3;
    const int K_eff = (flags & 4) ? min(K, ((int)blockIdx.y + 1) * 128) : K;
    const int nk = K_eff >> 5;

    const int r   = (tid >> 1) & 127;
    const int cc_ = tid & 1;
    const int rowA = m0 + r;
    const int rowB = n0 + r;
    const bool pA = rowA < M;
    const bool pB = rowB < N;
    const long long offA = (long long)(pA ? rowA : M - 1) * lda + cc_ * 16;
    const long long offB = (long long)(pB ? rowB : N - 1) * ldb + cc_ * 16;
    const uint32_t dstoff = (uint32_t)(r * HG_STRIDE + cc_ * 16) * 2;

    auto issue = [&](int kc, int s) {
        const uint32_t db = smem_base + (uint32_t)(s * HG_STAGE) * 2 + dstoff;
        const long long ko = (long long)kc * 32;
        cp16(db + 0 * HG_ARR * 2,      Ahi + offA + ko,     pA);
        cp16(db + 0 * HG_ARR * 2 + 16, Ahi + offA + ko + 8, pA);
        cp16(db + 1 * HG_ARR * 2,      Alo + offA + ko,     pA);
        cp16(db + 1 * HG_ARR * 2 + 16, Alo + offA + ko + 8, pA);
        cp16(db + 2 * HG_ARR * 2,      Bhi + offB + ko,     pB);
        cp16(db + 2 * HG_ARR * 2 + 16, Bhi + offB + ko + 8, pB);
        cp16(db + 3 * HG_ARR * 2,      Blo + offB + ko,     pB);
        cp16(db + 3 * HG_ARR * 2 + 16, Blo + offB + ko + 8, pB);
        CP_COMMIT();
    };

    const int a_row_off = (wm * 64 + (lane & 15)) * HG_STRIDE + (lane >> 4) * 8;
    const int b_row_off = (wn * 32 + (lane & 7)) * HG_STRIDE + ((lane >> 3) & 1) * 8;

    float acc[4][4][4];
#pragma unroll
    for (int i = 0; i < 4; i++)
#pragma unroll
        for (int j = 0; j < 4; j++)
#pragma unroll
            for (int q = 0; q < 4; q++) acc[i][j][q] = 0.f;

    auto compute = [&](int s) {
        const uint32_t base = smem_base + (uint32_t)(s * HG_STAGE) * 2;
#pragma unroll
        for (int kk = 0; kk < 32; kk += 16) {
            uint32_t bh[4][2], bl[4][2];
#pragma unroll
            for (int nt = 0; nt < 4; nt++) {
                const uint32_t boff = base + (2 * HG_ARR + b_row_off + nt * 8 * HG_STRIDE + kk) * 2;
                LDSM_X2(bh[nt][0], bh[nt][1], boff);
                LDSM_X2(bl[nt][0], bl[nt][1], boff + HG_ARR * 2);
            }
#pragma unroll
            for (int mt = 0; mt < 4; mt++) {
                uint32_t ah[4], al[4];
                const uint32_t aoff = base + (a_row_off + mt * 16 * HG_STRIDE + kk) * 2;
                LDSM_X4(ah[0], ah[1], ah[2], ah[3], aoff);
                LDSM_X4(al[0], al[1], al[2], al[3], aoff + HG_ARR * 2);
#pragma unroll
                for (int nt = 0; nt < 4; nt++) {
                    MMA_BF16(acc[mt][nt], ah, bh[nt]);
                    MMA_BF16(acc[mt][nt], ah, bl[nt]);
                    MMA_BF16(acc[mt][nt], al, bh[nt]);
                }
            }
        }
    };

    issue(0, 0);
    if (nk > 1) { issue(1, 1); CP_WAIT1(); }
    else        { CP_WAIT0(); }
    __syncthreads();

    for (int kc = 0; kc < nk; ++kc) {
        const int p = kc & 1;
        compute(p);
        __syncthreads();
        if (kc + 2 < nk) {
            issue(kc + 2, p);
            CP_WAIT1();
        } else {
            CP_WAIT0();
        }
        __syncthreads();
    }

    // ---- epilogue ----
    const int g  = lane >> 2;
    const int qc = (lane & 3) * 2;
#pragma unroll
    for (int mt = 0; mt < 4; mt++) {
        const int r0 = m0 + wm * 64 + mt * 16 + g;
        if (r0 >= M) continue;
#pragma unroll
        for (int nt = 0; nt < 4; nt++) {
            const int c = n0 + wn * 32 + nt * 8 + qc;
            if (c >= N) continue;
            float bx = 0.f, by = 0.f;
            if (bias) { bx = bias[c]; by = bias[c + 1]; }
            float2 v0 = make_float2(acc[mt][nt][0] + bx, acc[mt][nt][1] + by);
            float2 v1 = make_float2(acc[mt][nt][2] + bx, acc[mt][nt][3] + by);
            float* p0 = C + (long long)r0 * ldc + c;
            float* p1 = C + (long long)(r0 + 8) * ldc + c;
            if (flags & 1) {
                float2 o0 = *(const float2*)p0;
                v0.x += o0.x; v0.y += o0.y;
                if (r0 + 8 < M) {
                    float2 o1 = *(const float2*)p1;
                    v1.x += o1.x; v1.y += o1.y;
                }
            }
            if (flags & 8) {
                __nv_bfloat162 h2, l2;
                h2.x = __float2bfloat16(v0.x); h2.y = __float2bfloat16(v0.y);
                l2.x = __float2bfloat16(v0.x - __bfloat162float(h2.x));
                l2.y = __float2bfloat16(v0.y - __bfloat162float(h2.y));
                *(__nv_bfloat162*)(Chi + (long long)r0 * ldc + c) = h2;
                *(__nv_bfloat162*)(Clo + (long long)r0 * ldc + c) = l2;
                if (r0 + 8 < M) {
                    h2.x = __float2bfloat16(v1.x); h2.y = __float2bfloat16(v1.y);
                    l2.x = __float2bfloat16(v1.x - __bfloat162float(h2.x));
                    l2.y = __float2bfloat16(v1.y - __bfloat162float(h2.y));
                    *(__nv_bfloat162*)(Chi + (long long)(r0 + 8) * ldc + c) = h2;
                    *(__nv_bfloat162*)(Clo + (long long)(r0 + 8) * ldc + c) = l2;
                }
            } else {
                *(float2*)p0 = v0;
                if (r0 + 8 < M) *(float2*)p1 = v1;
            }
        }
    }
}

// ======================================================================
// RNN v3: column-split + per-CTA mbarrier sync (replaces barrier.cluster).
// Each CTA owns 2 phase-alternating mbarriers (count 512). Producers do
// remote store + remote arrive (release, cluster scope); consumers do a
// local try_wait (acquire, cluster scope). Two phases give sufficient
// backpressure (see analysis: a source reaches step s+2 only after the
// destination's s+1 arrivals, which follow its step-s consumption).
// ======================================================================
__global__ void __cluster_dims__(8, 1, 1) __launch_bounds__(512, 1)
rnn_kernel(const int* __restrict__ batch,
           const float* __restrict__ embproj,
           const float* __restrict__ W_hh,
           const float* __restrict__ b_hh,
           float* __restrict__ z,
           __nv_bfloat16* __restrict__ zhi,
           __nv_bfloat16* __restrict__ zlo)
{
    __shared__ float part[2][8][64];                   // [phase][src CTA][slot]
    __shared__ float hloc[64];                         // this CTA's own h chunk
    __shared__ alignas(8) unsigned long long mbar[2];  // phase barriers

    const int t    = threadIdx.x;
    const int rank = blockIdx.x & 7;
    const int b    = blockIdx.x >> 3;
    const int dst  = t >> 6;           // owner CTA of output t
    const int slot = t & 63;

    unsigned long long w2[32];
    {
        const ulonglong2* wp = (const ulonglong2*)(W_hh + (long long)t * H_ + rank * 64);
#pragma unroll
        for (int j = 0; j < 16; j++) {
            ulonglong2 v = wp[j];
            w2[2 * j]     = v.x;
            w2[2 * j + 1] = v.y;
        }
    }

    float bh = 0.f, xt = 0.f;
    if (t < 64) {
        bh = b_hh[rank * 64 + t];
        hloc[t] = 0.f;
        int tok = batch[b * L_ + 0];
        xt = embproj[(long long)tok * H_ + rank * 64 + t];
    }
    if (t < 2) {
        uint32_t ma = (uint32_t)__cvta_generic_to_shared(&mbar[t]);
        asm volatile("mbarrier.init.shared.b64 [%0], %1;" :: "r"(ma), "r"(512u) : "memory");
    }

    // remote addresses: partial slot and phase barrier inside CTA 'dst'
    uint32_t rpart[2], rmbar[2];
#pragma unroll
    for (int p = 0; p < 2; p++) {
        uint32_t la = (uint32_t)__cvta_generic_to_shared(&part[p][rank][slot]);
        asm volatile("mapa.shared::cluster.u32 %0, %1, %2;"
                     : "=r"(rpart[p]) : "r"(la), "r"(dst));
        uint32_t lb = (uint32_t)__cvta_generic_to_shared(&mbar[p]);
        asm volatile("mapa.shared::cluster.u32 %0, %1, %2;"
                     : "=r"(rmbar[p]) : "r"(lb), "r"(dst));
    }
    __syncthreads();
    // all CTAs' mbarrier inits must be visible before any remote arrive
    asm volatile("barrier.cluster.arrive.aligned;" ::: "memory");
    asm volatile("barrier.cluster.wait.aligned;"   ::: "memory");

    for (int step = 0; step < L_; ++step) {
        const int p   = step & 1;
        const uint32_t par = (uint32_t)((step >> 1) & 1);

        const ulonglong2* h2 = (const ulonglong2*)hloc;
        unsigned long long acc = 0ULL;
#pragma unroll
        for (int j = 0; j < 16; j++) {
            ulonglong2 hv = h2[j];
            asm("fma.rn.f32x2 %0, %1, %2, %0;" : "+l"(acc) : "l"(w2[2*j]),   "l"(hv.x));
            asm("fma.rn.f32x2 %0, %1, %2, %0;" : "+l"(acc) : "l"(w2[2*j+1]), "l"(hv.y));
        }
        float sx, sy;
        asm("mov.b64 {%0, %1}, %2;" : "=f"(sx), "=f"(sy) : "l"(acc));
        const float s = sx + sy;
        asm volatile("st.shared::cluster.f32 [%0], %1;"
                     :: "r"(rpart[p]), "f"(s) : "memory");
        asm volatile("mbarrier.arrive.release.cluster.shared::cluster.b64 _, [%0];"
                     :: "r"(rmbar[p]) : "memory");

        // prefetch next x_proj while arrivals propagate
        float xtn = 0.f;
        if (t < 64 && step + 1 < L_) {
            int tk = batch[b * L_ + step + 1];
            xtn = embproj[(long long)tk * H_ + rank * 64 + t];
        }

        // wait for all 512 arrivals on this phase's local barrier
        {
            const uint32_t ma = (uint32_t)__cvta_generic_to_shared(&mbar[p]);
            uint32_t done;
            asm volatile("{\n\t.reg .pred q;\n\t"
                "mbarrier.try_wait.parity.acquire.cluster.shared::cta.b64 q, [%1], %2;\n\t"
                "selp.b32 %0, 1, 0, q;\n\t}"
                : "=r"(done) : "r"(ma), "r"(par) : "memory");
            if (!done) {
                asm volatile("{\n\t.reg .pred q;\n\t"
                    "WL_%=:\n\t"
                    "mbarrier.try_wait.parity.acquire.cluster.shared::cta.b64 q, [%0], %1, 0x989680;\n\t"
                    "@q bra.uni WD_%=;\n\t"
                    "bra.uni WL_%=;\n\t"
                    "WD_%=:\n\t}"
                    :: "r"(ma), "r"(par) : "memory");
            }
        }

        if (t < 64) {
            float v = part[p][0][t] + part[p][1][t] + part[p][2][t] + part[p][3][t]
                    + part[p][4][t] + part[p][5][t] + part[p][6][t] + part[p][7][t];
            v = tanhf(xt + v + bh);
            const long long zo = ((long long)(b * L_ + step)) * H_ + rank * 64 + t;
            z[zo] = v;
            __nv_bfloat16 vh = __float2bfloat16(v);
            zhi[zo] = vh;
            zlo[zo] = __float2bfloat16(v - __bfloat162float(vh));
            hloc[t] = v;
        }
        __syncthreads();
        xt = xtn;
    }

    // no CTA may exit while peers could still address its smem
    asm volatile("barrier.cluster.arrive.aligned;" ::: "memory");
    asm volatile("barrier.cluster.wait.aligned;"   ::: "memory");
}

// ======================================================================
// Row softmax: fp32 scores -> probs bf16 hi/lo (+zero pad to diag tile)
// ======================================================================
__global__ __launch_bounds__(256) void softmax_rows(
    const float* __restrict__ S,
    __nv_bfloat16* __restrict__ Phi, __nv_bfloat16* __restrict__ Plo)
{
    const int i = blockIdx.x;
    const int b = blockIdx.y;
    const float* row = S + (size_t)b * LL + (size_t)i * L_;
    __nv_bfloat16* rh = Phi + (size_t)b * LL + (size_t)i * L_;
    __nv_bfloat16* rl = Plo + (size_t)b * LL + (size_t)i * L_;
    const int len = i;
    const int tileEnd = ((i >> 7) + 1) << 7;
    const int tid = threadIdx.x;

    __shared__ float sm_[8];
    __shared__ float bc[2];

    if (len > 0) {
        float m = -1e30f;
        for (int j = tid; j < len; j += 256) m = fmaxf(m, row[j]);
#pragma unroll
        for (int o = 16; o; o >>= 1) m = fmaxf(m, __shfl_xor_sync(~0u, m, o));
        if ((tid & 31) == 0) sm_[tid >> 5] = m;
        __syncthreads();
        if (tid == 0) {
            float v = sm_[0];
            for (int wgt = 1; wgt < 8; wgt++) v = fmaxf(v, sm_[wgt]);
            bc[0] = v;
        }
        __syncthreads();
        m = bc[0];

        float s = 0.f;
        for (int j = tid; j < len; j += 256) s += expf(row[j] - m);
#pragma unroll
        for (int o = 16; o; o >>= 1) s += __shfl_xor_sync(~0u, s, o);
        if ((tid & 31) == 0) sm_[tid >> 5] = s;
        __syncthreads();
        if (tid == 0) {
            float v = sm_[0];
            for (int wgt = 1; wgt < 8; wgt++) v += sm_[wgt];
            bc[1] = 1.f / v;
        }
        __syncthreads();
        const float inv = bc[1];

        for (int j = tid; j < len; j += 256) {
            float pv = expf(row[j] - m) * inv;
            __nv_bfloat16 h = __float2bfloat16(pv);
            rh[j] = h;
            rl[j] = __float2bfloat16(pv - __bfloat162float(h));
        }
    }
    const __nv_bfloat16 zz = __float2bfloat16(0.f);
    for (int j = len + tid; j < tileEnd; j += 256) { rh[j] = zz; rl[j] = zz; }
}

// ======================================================================
// z [B,L,H] fp32 -> z^T [B,H,L] bf16 hi/lo
// ======================================================================
__global__ __launch_bounds__(256) void transpose_split(
    const float* __restrict__ z,
    __nv_bfloat16* __restrict__ Thi, __nv_bfloat16* __restrict__ Tlo)
{
    __shared__ float tile[32][33];
    const int b  = blockIdx.z;
    const int l0 = blockIdx.x * 32;
    const int h0 = blockIdx.y * 32;
    const int tx = threadIdx.x & 31;
    const int ty = threadIdx.x >> 5;

    const float* zb = z + (size_t)b * LH;
#pragma unroll
    for (int i = ty; i < 32; i += 8)
        tile[i][tx] = zb[(long long)(l0 + i) * H_ + h0 + tx];
    __syncthreads();

    __nv_bfloat16* th = Thi + (size_t)b * H_ * L_;
    __nv_bfloat16* tl = Tlo + (size_t)b * H_ * L_;
#pragma unroll
    for (int i = ty; i < 32; i += 8) {
        float v = tile[tx][i];
        __nv_bfloat16 h = __float2bfloat16(v);
        const long long o = (long long)(h0 + i) * L_ + l0 + tx;
        th[o] = h;
        tl[o] = __float2bfloat16(v - __bfloat162float(h));
    }
}

// ======================================================================
// av row 0 = mean of z -> written directly as bf16 hi/lo
// ======================================================================
__global__ __launch_bounds__(512) void av0_mean(const float* __restrict__ z,
                                                __nv_bfloat16* __restrict__ avhi,
                                                __nv_bfloat16* __restrict__ avlo)
{
    const int b = blockIdx.x;
    const float4* zb = (const float4*)(z + (size_t)b * LH);
    const int tid = threadIdx.x;
    const int hc = tid & 127;
    const int jg = tid >> 7;

    float4 acc = make_float4(0.f, 0.f, 0.f, 0.f);
#pragma unroll 8
    for (int j = jg * 512; j < (jg + 1) * 512; j++) {
        float4 v = zb[(long long)j * 128 + hc];
        acc.x += v.x; acc.y += v.y; acc.z += v.z; acc.w += v.w;
    }
    __shared__ float4 part[4][128];
    part[jg][hc] = acc;
    __syncthreads();
    if (tid < 128) {
        float4 s = part[0][tid];
        float4 p1 = part[1][tid], p2 = part[2][tid], p3 = part[3][tid];
        float vv[4];
        vv[0] = (s.x + p1.x + p2.x + p3.x) * (1.f / L_);
        vv[1] = (s.y + p1.y + p2.y + p3.y) * (1.f / L_);
        vv[2] = (s.z + p1.z + p2.z + p3.z) * (1.f / L_);
        vv[3] = (s.w + p1.w + p2.w + p3.w) * (1.f / L_);
        __nv_bfloat16* ah = avhi + (size_t)b * LH + tid * 4;
        __nv_bfloat16* al = avlo + (size_t)b * LH + tid * 4;
#pragma unroll
        for (int q = 0; q < 4; q++) {
            __nv_bfloat16 h = __float2bfloat16(vv[q]);
            ah[q] = h;
            al[q] = __float2bfloat16(vv[q] - __bfloat162float(h));
        }
    }
}

// ======================================================================
// split fp32 -> (bf16 hi, bf16 lo)
// ======================================================================
__global__ __launch_bounds__(1024) void split_bf16(
    const float* __restrict__ x, __nv_bfloat16* __restrict__ hi,
    __nv_bfloat16* __restrict__ lo, int n)
{
    int i = blockIdx.x * 1024 + threadIdx.x;
    if (i < n) {
        float v = x[i];
        __nv_bfloat16 h = __float2bfloat16(v);
        hi[i] = h;
        lo[i] = __float2bfloat16(v - __bfloat162float(h));
    }
}

// ======================================================================
extern "C" void kernel_launch(void* const* d_in, const int* in_sizes, int n_in,
                              void* d_out, int out_size)
{
    const int*   batch = (const int*)  d_in[0];
    const float* emb   = (const float*)d_in[1];
    const float* W_ih  = (const float*)d_in[2];
    const float* b_ih  = (const float*)d_in[3];
    const float* W_hh  = (const float*)d_in[4];
    const float* b_hh  = (const float*)d_in[5];
    const float* W_c   = (const float*)d_in[6];
    const float* b_c   = (const float*)d_in[7];
    const float* W_d   = (const float*)d_in[8];
    const float* b_d   = (const float*)d_in[9];
    float* out = (float*)d_out;

    float *embproj, *zbuf, *Pbuf, *decbuf;
    __nv_bfloat16 *phi, *plo, *zthi, *ztlo;
    __nv_bfloat16 *dhi, *dlo, *wdhi, *wdlo, *zhi, *zlo, *avhi, *avlo;
    __nv_bfloat16 *ehi, *elo, *wihhi, *wihlo, *wchi, *wclo;
    cudaGetSymbolAddress((void**)&embproj, g_embproj);
    cudaGetSymbolAddress((void**)&zbuf,    g_z);
    cudaGetSymbolAddress((void**)&Pbuf,    g_P);
    cudaGetSymbolAddress((void**)&decbuf,  g_dec);
    cudaGetSymbolAddress((void**)&phi,     g_P_hi);
    cudaGetSymbolAddress((void**)&plo,     g_P_lo);
    cudaGetSymbolAddress((void**)&zthi,    g_zT_hi);
    cudaGetSymbolAddress((void**)&ztlo,    g_zT_lo);
    cudaGetSymbolAddress((void**)&dhi,     g_dec_hi);
    cudaGetSymbolAddress((void**)&dlo,     g_dec_lo);
    cudaGetSymbolAddress((void**)&wdhi,    g_wd_hi);
    cudaGetSymbolAddress((void**)&wdlo,    g_wd_lo);
    cudaGetSymbolAddress((void**)&zhi,     g_z_hi);
    cudaGetSymbolAddress((void**)&zlo,     g_z_lo);
    cudaGetSymbolAddress((void**)&avhi,    g_av_hi);
    cudaGetSymbolAddress((void**)&avlo,    g_av_lo);
    cudaGetSymbolAddress((void**)&ehi,     g_emb_hi);
    cudaGetSymbolAddress((void**)&elo,     g_emb_lo);
    cudaGetSymbolAddress((void**)&wihhi,   g_wih_hi);
    cudaGetSymbolAddress((void**)&wihlo,   g_wih_lo);
    cudaGetSymbolAddress((void**)&wchi,    g_wc_hi);
    cudaGetSymbolAddress((void**)&wclo,    g_wc_lo);

    cudaFuncSetAttribute(hgemm_nt, cudaFuncAttributeMaxDynamicSharedMemorySize, HG_SMEM);

    static cudaStream_t s2 = nullptr;
    static cudaEvent_t evZ = nullptr, evT = nullptr, evDecZ = nullptr;
    if (!s2) {
        cudaStreamCreateWithFlags(&s2, cudaStreamNonBlocking);
        cudaEventCreateWithFlags(&evZ,    cudaEventDisableTiming);
        cudaEventCreateWithFlags(&evT,    cudaEventDisableTiming);
        cudaEventCreateWithFlags(&evDecZ, cudaEventDisableTiming);
    }

    const int ML = B_ * L_;   // 16384

    // ---- side stream: W_c / W_d splits overlap with the main head ----
    split_bf16<<<(H_ * 2 * H_ + 1023) / 1024, 1024, 0, s2>>>(W_c, wchi, wclo, H_ * 2 * H_);
    split_bf16<<<(V_ * H_ + 1023) / 1024, 1024, 0, s2>>>(W_d, wdhi, wdlo, V_ * H_);

    // ---- main: emb/W_ih splits -> embproj -> RNN ----
    split_bf16<<<(V_ * H_ + 1023) / 1024, 1024>>>(emb, ehi, elo, V_ * H_);
    split_bf16<<<(H_ * H_ + 1023) / 1024, 1024>>>(W_ih, wihhi, wihlo, H_ * H_);

    hgemm_nt<<<dim3(4, 79, 1), 256, HG_SMEM>>>(
        ehi, elo, H_, 0, wihhi, wihlo, H_, 0,
        embproj, nullptr, nullptr, H_, 0, V_, H_, H_, b_ih, 0);

    rnn_kernel<<<64, 512>>>(batch, embproj, W_hh, b_hh, zbuf, zhi, zlo);
    cudaEventRecord(evZ, 0);

    // ---- side branch: transpose + z-part decoder GEMM (with bias) ----
    cudaStreamWaitEvent(s2, evZ, 0);
    transpose_split<<<dim3(L_ / 32, H_ / 32, B_), 256, 0, s2>>>(zbuf, zthi, ztlo);
    cudaEventRecord(evT, s2);
    hgemm_nt<<<dim3(4, 128, 1), 256, HG_SMEM, s2>>>(
        zhi, zlo, H_, 0, wchi + H_, wclo + H_, 2 * H_, 0,
        decbuf, nullptr, nullptr, H_, 0, ML, H_, H_, b_c, 0);
    cudaEventRecord(evDecZ, s2);

    // ---- main branch: attention chain ----
    hgemm_nt<<<dim3(16, 16, B_), 256, HG_SMEM>>>(
        zhi, zlo, H_, LH, zhi, zlo, H_, LH,
        Pbuf, nullptr, nullptr, L_, LL, L_, L_, H_, nullptr, 2);

    softmax_rows<<<dim3(L_, B_), 256>>>(Pbuf, phi, plo);

    // av = P @ z^T  (causal K-limit, fused bf16-split output)
    cudaStreamWaitEvent(0, evT, 0);
    hgemm_nt<<<dim3(4, 16, B_), 256, HG_SMEM>>>(
        phi, plo, L_, LL, zthi, ztlo, L_, (long long)H_ * L_,
        nullptr, avhi, avlo, H_, LH, L_, H_, L_, nullptr, 4 | 8);

    // fix row 0: uniform attention -> mean of z, written as hi/lo
    av0_mean<<<B_, 512>>>(zbuf, avhi, avlo);

    // dec += av @ W_c[:, :H]^T  (accumulate fp32 dec, emit bf16 hi/lo)
    cudaStreamWaitEvent(0, evDecZ, 0);
    hgemm_nt<<<dim3(4, 128, 1), 256, HG_SMEM>>>(
        avhi, avlo, H_, 0, wchi, wclo, 2 * H_, 0,
        decbuf, dhi, dlo, H_, 0, ML, H_, H_, nullptr, 1 | 8);

    // logits = dec @ W_d^T + b_d
    hgemm_nt<<<dim3(79, 128, 1), 256, HG_SMEM>>>(
        dhi, dlo, H_, 0, wdhi, wdlo, H_, 0,
        out, nullptr, nullptr, V_, 0, ML, V_, H_, b_d, 0);
}

// round 16
// speedup vs baseline: 1.1581x; 1.1581x over previous
#include <cuda_runtime.h>
#include <cuda_bf16.h>
#include <cstdint>

#define B_ 8
#define L_ 2048
#define V_ 10000
#define H_ 512

static const long long LH = (long long)L_ * H_;       // 1048576
static const long long LL = (long long)L_ * L_;       // 4194304

// ---------------- static device scratch (no allocations) ----------------
__device__ float g_embproj[V_ * H_];                   // 20.5 MB
__device__ float g_z[B_ * L_ * H_];                    // 33.5 MB
__device__ float g_P[(size_t)B_ * L_ * L_];            // 134 MB (raw scores)
__device__ float g_dec[B_ * L_ * H_];                  // 33.5 MB

__device__ __nv_bfloat16 g_P_hi[(size_t)B_ * L_ * L_]; // 67 MB (probs hi)
__device__ __nv_bfloat16 g_P_lo[(size_t)B_ * L_ * L_]; // 67 MB (probs lo)
__device__ __nv_bfloat16 g_zT_hi[B_ * H_ * L_];        // 16.8 MB (z^T)
__device__ __nv_bfloat16 g_zT_lo[B_ * H_ * L_];
__device__ __nv_bfloat16 g_dec_hi[B_ * L_ * H_];
__device__ __nv_bfloat16 g_dec_lo[B_ * L_ * H_];
__device__ __nv_bfloat16 g_wd_hi[V_ * H_];
__device__ __nv_bfloat16 g_wd_lo[V_ * H_];
__device__ __nv_bfloat16 g_z_hi[B_ * L_ * H_];
__device__ __nv_bfloat16 g_z_lo[B_ * L_ * H_];
__device__ __nv_bfloat16 g_av_hi[B_ * L_ * H_];
__device__ __nv_bfloat16 g_av_lo[B_ * L_ * H_];
__device__ __nv_bfloat16 g_emb_hi[V_ * H_];
__device__ __nv_bfloat16 g_emb_lo[V_ * H_];
__device__ __nv_bfloat16 g_wih_hi[H_ * H_];
__device__ __nv_bfloat16 g_wih_lo[H_ * H_];
__device__ __nv_bfloat16 g_wc_hi[H_ * 2 * H_];
__device__ __nv_bfloat16 g_wc_lo[H_ * 2 * H_];

__device__ __forceinline__ uint32_t smem_u32(const void* p) {
    uint32_t a;
    asm("{ .reg .u64 t; cvta.to.shared.u64 t, %1; cvt.u32.u64 %0, t; }"
        : "=r"(a) : "l"(p));
    return a;
}

#define LDSM_X4(r0, r1, r2, r3, addr)                                         \
    asm volatile("ldmatrix.sync.aligned.m8n8.x4.shared.b16 {%0,%1,%2,%3}, [%4];" \
                 : "=r"(r0), "=r"(r1), "=r"(r2), "=r"(r3) : "r"(addr))
#define LDSM_X2(r0, r1, addr)                                                 \
    asm volatile("ldmatrix.sync.aligned.m8n8.x2.shared.b16 {%0,%1}, [%2];"    \
                 : "=r"(r0), "=r"(r1) : "r"(addr))
#define MMA_BF16(c, a, b)                                                     \
    asm volatile("mma.sync.aligned.m16n8k16.row.col.f32.bf16.bf16.f32 "       \
                 "{%0,%1,%2,%3}, {%4,%5,%6,%7}, {%8,%9}, {%0,%1,%2,%3};"      \
                 : "+f"((c)[0]), "+f"((c)[1]), "+f"((c)[2]), "+f"((c)[3])     \
                 : "r"((a)[0]), "r"((a)[1]), "r"((a)[2]), "r"((a)[3]),        \
                   "r"((b)[0]), "r"((b)[1]))

__device__ __forceinline__ void cp16(uint32_t dst, const void* src, bool pred) {
    int sz = pred ? 16 : 0;
    asm volatile("cp.async.cg.shared.global [%0], [%1], 16, %2;"
                 :: "r"(dst), "l"(src), "r"(sz));
}
#define CP_COMMIT() asm volatile("cp.async.commit_group;" ::: "memory")
#define CP_WAIT1()  asm volatile("cp.async.wait_group 1;" ::: "memory")
#define CP_WAIT0()  asm volatile("cp.async.wait_group 0;" ::: "memory")

// ======================================================================
// Generic split-bf16 HMMA NT GEMM (2-stage cp.async, 2 CTAs/SM):
//   C[M,N] = (Ahi+Alo)[M,K] @ (Bhi+Blo)[N,K]^T (+bias) (+=C)
// flags: bit0 = accumulate (reads fp32 C), bit1 = causal tile skip,
//        bit2 = causal K-limit, bit3 = write output as bf16 hi/lo
// ======================================================================
#define HG_STRIDE 40
#define HG_ARR    (128 * HG_STRIDE)              // 5120 bf16 per array
#define HG_STAGE  (4 * HG_ARR)                   // per stage (Ahi,Alo,Bhi,Blo)
#define HG_SMEM   (2 * HG_STAGE * 2)             // 81920 bytes (2 stages)

__global__ __launch_bounds__(256, 2) void hgemm_nt(
    const __nv_bfloat16* __restrict__ Ahi, const __nv_bfloat16* __restrict__ Alo,
    int lda, long long sA,
    const __nv_bfloat16* __restrict__ Bhi, const __nv_bfloat16* __restrict__ Blo,
    int ldb, long long sB,
    float* __restrict__ C,
    __nv_bfloat16* __restrict__ Chi, __nv_bfloat16* __restrict__ Clo,
    int ldc, long long sC,
    int M, int N, int K,
    const float* __restrict__ bias, int flags)
{
    if ((flags & 2) && blockIdx.x > blockIdx.y) return;
    Ahi += (long long)blockIdx.z * sA;  Alo += (long long)blockIdx.z * sA;
    Bhi += (long long)blockIdx.z * sB;  Blo += (long long)blockIdx.z * sB;
    C   += (long long)blockIdx.z * sC;
    if (Chi) { Chi += (long long)blockIdx.z * sC; Clo += (long long)blockIdx.z * sC; }

    extern __shared__ __nv_bfloat16 sm[];
    const uint32_t smem_base = smem_u32(sm);
    const int tid  = threadIdx.x;
    const int wid  = tid >> 5;
    const int lane = tid & 31;
    const int m0 = blockIdx.y * 128;
    const int n0 = blockIdx.x * 128;
    const int wm = wid >> 2;
    const int wn = wid & 3;
    const int K_eff = (flags & 4) ? min(K, ((int)blockIdx.y + 1) * 128) : K;
    const int nk = K_eff >> 5;

    const int r   = (tid >> 1) & 127;
    const int cc_ = tid & 1;
    const int rowA = m0 + r;
    const int rowB = n0 + r;
    const bool pA = rowA < M;
    const bool pB = rowB < N;
    const long long offA = (long long)(pA ? rowA : M - 1) * lda + cc_ * 16;
    const long long offB = (long long)(pB ? rowB : N - 1) * ldb + cc_ * 16;
    const uint32_t dstoff = (uint32_t)(r * HG_STRIDE + cc_ * 16) * 2;

    auto issue = [&](int kc, int s) {
        const uint32_t db = smem_base + (uint32_t)(s * HG_STAGE) * 2 + dstoff;
        const long long ko = (long long)kc * 32;
        cp16(db + 0 * HG_ARR * 2,      Ahi + offA + ko,     pA);
        cp16(db + 0 * HG_ARR * 2 + 16, Ahi + offA + ko + 8, pA);
        cp16(db + 1 * HG_ARR * 2,      Alo + offA + ko,     pA);
        cp16(db + 1 * HG_ARR * 2 + 16, Alo + offA + ko + 8, pA);
        cp16(db + 2 * HG_ARR * 2,      Bhi + offB + ko,     pB);
        cp16(db + 2 * HG_ARR * 2 + 16, Bhi + offB + ko + 8, pB);
        cp16(db + 3 * HG_ARR * 2,      Blo + offB + ko,     pB);
        cp16(db + 3 * HG_ARR * 2 + 16, Blo + offB + ko + 8, pB);
        CP_COMMIT();
    };

    const int a_row_off = (wm * 64 + (lane & 15)) * HG_STRIDE + (lane >> 4) * 8;
    const int b_row_off = (wn * 32 + (lane & 7)) * HG_STRIDE + ((lane >> 3) & 1) * 8;

    float acc[4][4][4];
#pragma unroll
    for (int i = 0; i < 4; i++)
#pragma unroll
        for (int j = 0; j < 4; j++)
#pragma unroll
            for (int q = 0; q < 4; q++) acc[i][j][q] = 0.f;

    auto compute = [&](int s) {
        const uint32_t base = smem_base + (uint32_t)(s * HG_STAGE) * 2;
#pragma unroll
        for (int kk = 0; kk < 32; kk += 16) {
            uint32_t bh[4][2], bl[4][2];
#pragma unroll
            for (int nt = 0; nt < 4; nt++) {
                const uint32_t boff = base + (2 * HG_ARR + b_row_off + nt * 8 * HG_STRIDE + kk) * 2;
                LDSM_X2(bh[nt][0], bh[nt][1], boff);
                LDSM_X2(bl[nt][0], bl[nt][1], boff + HG_ARR * 2);
            }
#pragma unroll
            for (int mt = 0; mt < 4; mt++) {
                uint32_t ah[4], al[4];
                const uint32_t aoff = base + (a_row_off + mt * 16 * HG_STRIDE + kk) * 2;
                LDSM_X4(ah[0], ah[1], ah[2], ah[3], aoff);
                LDSM_X4(al[0], al[1], al[2], al[3], aoff + HG_ARR * 2);
#pragma unroll
                for (int nt = 0; nt < 4; nt++) {
                    MMA_BF16(acc[mt][nt], ah, bh[nt]);
                    MMA_BF16(acc[mt][nt], ah, bl[nt]);
                    MMA_BF16(acc[mt][nt], al, bh[nt]);
                }
            }
        }
    };

    issue(0, 0);
    if (nk > 1) { issue(1, 1); CP_WAIT1(); }
    else        { CP_WAIT0(); }
    __syncthreads();

    for (int kc = 0; kc < nk; ++kc) {
        const int p = kc & 1;
        compute(p);
        __syncthreads();
        if (kc + 2 < nk) {
            issue(kc + 2, p);
            CP_WAIT1();
        } else {
            CP_WAIT0();
        }
        __syncthreads();
    }

    // ---- epilogue ----
    const int g  = lane >> 2;
    const int qc = (lane & 3) * 2;
#pragma unroll
    for (int mt = 0; mt < 4; mt++) {
        const int r0 = m0 + wm * 64 + mt * 16 + g;
        if (r0 >= M) continue;
#pragma unroll
        for (int nt = 0; nt < 4; nt++) {
            const int c = n0 + wn * 32 + nt * 8 + qc;
            if (c >= N) continue;
            float bx = 0.f, by = 0.f;
            if (bias) { bx = bias[c]; by = bias[c + 1]; }
            float2 v0 = make_float2(acc[mt][nt][0] + bx, acc[mt][nt][1] + by);
            float2 v1 = make_float2(acc[mt][nt][2] + bx, acc[mt][nt][3] + by);
            float* p0 = C + (long long)r0 * ldc + c;
            float* p1 = C + (long long)(r0 + 8) * ldc + c;
            if (flags & 1) {
                float2 o0 = *(const float2*)p0;
                v0.x += o0.x; v0.y += o0.y;
                if (r0 + 8 < M) {
                    float2 o1 = *(const float2*)p1;
                    v1.x += o1.x; v1.y += o1.y;
                }
            }
            if (flags & 8) {
                __nv_bfloat162 h2, l2;
                h2.x = __float2bfloat16(v0.x); h2.y = __float2bfloat16(v0.y);
                l2.x = __float2bfloat16(v0.x - __bfloat162float(h2.x));
                l2.y = __float2bfloat16(v0.y - __bfloat162float(h2.y));
                *(__nv_bfloat162*)(Chi + (long long)r0 * ldc + c) = h2;
                *(__nv_bfloat162*)(Clo + (long long)r0 * ldc + c) = l2;
                if (r0 + 8 < M) {
                    h2.x = __float2bfloat16(v1.x); h2.y = __float2bfloat16(v1.y);
                    l2.x = __float2bfloat16(v1.x - __bfloat162float(h2.x));
                    l2.y = __float2bfloat16(v1.y - __bfloat162float(h2.y));
                    *(__nv_bfloat162*)(Chi + (long long)(r0 + 8) * ldc + c) = h2;
                    *(__nv_bfloat162*)(Clo + (long long)(r0 + 8) * ldc + c) = l2;
                }
            } else {
                *(float2*)p0 = v0;
                if (r0 + 8 < M) *(float2*)p1 = v1;
            }
        }
    }
}

// ======================================================================
// RNN (column-split, f32x2 FMA, barrier.cluster — R13-proven version)
// ======================================================================
__global__ void __cluster_dims__(8, 1, 1) __launch_bounds__(512, 1)
rnn_kernel(const int* __restrict__ batch,
           const float* __restrict__ embproj,
           const float* __restrict__ W_hh,
           const float* __restrict__ b_hh,
           float* __restrict__ z,
           __nv_bfloat16* __restrict__ zhi,
           __nv_bfloat16* __restrict__ zlo)
{
    __shared__ float part[2][8][64];   // [phase][src CTA][slot]
    __shared__ float hloc[64];         // this CTA's own h chunk

    const int t    = threadIdx.x;
    const int rank = blockIdx.x & 7;
    const int b    = blockIdx.x >> 3;
    const int dst  = t >> 6;           // owner CTA of output t
    const int slot = t & 63;

    unsigned long long w2[32];
    {
        const ulonglong2* wp = (const ulonglong2*)(W_hh + (long long)t * H_ + rank * 64);
#pragma unroll
        for (int j = 0; j < 16; j++) {
            ulonglong2 v = wp[j];
            w2[2 * j]     = v.x;
            w2[2 * j + 1] = v.y;
        }
    }

    float bh = 0.f, xt = 0.f;
    if (t < 64) {
        bh = b_hh[rank * 64 + t];
        hloc[t] = 0.f;
        int tok = batch[b * L_ + 0];
        xt = embproj[(long long)tok * H_ + rank * 64 + t];
    }

    uint32_t rpart[2];
#pragma unroll
    for (int p = 0; p < 2; p++) {
        uint32_t la = (uint32_t)__cvta_generic_to_shared(&part[p][rank][slot]);
        asm volatile("mapa.shared::cluster.u32 %0, %1, %2;"
                     : "=r"(rpart[p]) : "r"(la), "r"(dst));
    }
    __syncthreads();
    asm volatile("barrier.cluster.arrive.aligned;" ::: "memory");
    asm volatile("barrier.cluster.wait.aligned;"   ::: "memory");

    for (int step = 0; step < L_; ++step) {
        const int p = step & 1;
        const ulonglong2* h2 = (const ulonglong2*)hloc;
        unsigned long long acc = 0ULL;
#pragma unroll
        for (int j = 0; j < 16; j++) {
            ulonglong2 hv = h2[j];
            asm("fma.rn.f32x2 %0, %1, %2, %0;" : "+l"(acc) : "l"(w2[2*j]),   "l"(hv.x));
            asm("fma.rn.f32x2 %0, %1, %2, %0;" : "+l"(acc) : "l"(w2[2*j+1]), "l"(hv.y));
        }
        float sx, sy;
        asm("mov.b64 {%0, %1}, %2;" : "=f"(sx), "=f"(sy) : "l"(acc));
        const float s = sx + sy;
        asm volatile("st.shared::cluster.f32 [%0], %1;"
                     :: "r"(rpart[p]), "f"(s) : "memory");

        float xtn = 0.f;
        if (t < 64 && step + 1 < L_) {
            int tk = batch[b * L_ + step + 1];
            xtn = embproj[(long long)tk * H_ + rank * 64 + t];
        }

        asm volatile("barrier.cluster.arrive.aligned;" ::: "memory");
        asm volatile("barrier.cluster.wait.aligned;"   ::: "memory");

        if (t < 64) {
            float v = part[p][0][t] + part[p][1][t] + part[p][2][t] + part[p][3][t]
                    + part[p][4][t] + part[p][5][t] + part[p][6][t] + part[p][7][t];
            v = tanhf(xt + v + bh);
            const long long zo = ((long long)(b * L_ + step)) * H_ + rank * 64 + t;
            z[zo] = v;
            __nv_bfloat16 vh = __float2bfloat16(v);
            zhi[zo] = vh;
            zlo[zo] = __float2bfloat16(v - __bfloat162float(vh));
            hloc[t] = v;
        }
        __syncthreads();
        xt = xtn;
    }
}

// ======================================================================
// Row softmax (single global read): stream row into smem while computing
// max; exp out of smem for the sum; write bf16 hi/lo from smem.
// ======================================================================
__global__ __launch_bounds__(256) void softmax_rows(
    const float* __restrict__ S,
    __nv_bfloat16* __restrict__ Phi, __nv_bfloat16* __restrict__ Plo)
{
    __shared__ float ebuf[2048];
    __shared__ float sm_[8];
    __shared__ float bc[2];

    const int i = blockIdx.x;
    const int b = blockIdx.y;
    const float* row = S + (size_t)b * LL + (size_t)i * L_;
    __nv_bfloat16* rh = Phi + (size_t)b * LL + (size_t)i * L_;
    __nv_bfloat16* rl = Plo + (size_t)b * LL + (size_t)i * L_;
    const int len = i;
    const int tileEnd = ((i >> 7) + 1) << 7;
    const int tid = threadIdx.x;

    if (len > 0) {
        // pass 1: single global read -> smem, compute max
        float m = -1e30f;
        for (int j = tid; j < len; j += 256) {
            float v = row[j];
            ebuf[j] = v;
            m = fmaxf(m, v);
        }
#pragma unroll
        for (int o = 16; o; o >>= 1) m = fmaxf(m, __shfl_xor_sync(~0u, m, o));
        if ((tid & 31) == 0) sm_[tid >> 5] = m;
        __syncthreads();
        if (tid == 0) {
            float v = sm_[0];
            for (int wgt = 1; wgt < 8; wgt++) v = fmaxf(v, sm_[wgt]);
            bc[0] = v;
        }
        __syncthreads();
        m = bc[0];

        // pass 2: exp from smem (overwrite in place), accumulate sum
        float s = 0.f;
        for (int j = tid; j < len; j += 256) {
            float e = expf(ebuf[j] - m);
            ebuf[j] = e;
            s += e;
        }
#pragma unroll
        for (int o = 16; o; o >>= 1) s += __shfl_xor_sync(~0u, s, o);
        if ((tid & 31) == 0) sm_[tid >> 5] = s;
        __syncthreads();
        if (tid == 0) {
            float v = sm_[0];
            for (int wgt = 1; wgt < 8; wgt++) v += sm_[wgt];
            bc[1] = 1.f / v;
        }
        __syncthreads();
        const float inv = bc[1];

        // pass 3: write probabilities from smem
        for (int j = tid; j < len; j += 256) {
            float pv = ebuf[j] * inv;
            __nv_bfloat16 h = __float2bfloat16(pv);
            rh[j] = h;
            rl[j] = __float2bfloat16(pv - __bfloat162float(h));
        }
    }
    const __nv_bfloat16 zz = __float2bfloat16(0.f);
    for (int j = len + tid; j < tileEnd; j += 256) { rh[j] = zz; rl[j] = zz; }
}

// ======================================================================
// z [B,L,H] fp32 -> z^T [B,H,L] bf16 hi/lo
// ======================================================================
__global__ __launch_bounds__(256) void transpose_split(
    const float* __restrict__ z,
    __nv_bfloat16* __restrict__ Thi, __nv_bfloat16* __restrict__ Tlo)
{
    __shared__ float tile[32][33];
    const int b  = blockIdx.z;
    const int l0 = blockIdx.x * 32;
    const int h0 = blockIdx.y * 32;
    const int tx = threadIdx.x & 31;
    const int ty = threadIdx.x >> 5;

    const float* zb = z + (size_t)b * LH;
#pragma unroll
    for (int i = ty; i < 32; i += 8)
        tile[i][tx] = zb[(long long)(l0 + i) * H_ + h0 + tx];
    __syncthreads();

    __nv_bfloat16* th = Thi + (size_t)b * H_ * L_;
    __nv_bfloat16* tl = Tlo + (size_t)b * H_ * L_;
#pragma unroll
    for (int i = ty; i < 32; i += 8) {
        float v = tile[tx][i];
        __nv_bfloat16 h = __float2bfloat16(v);
        const long long o = (long long)(h0 + i) * L_ + l0 + tx;
        th[o] = h;
        tl[o] = __float2bfloat16(v - __bfloat162float(h));
    }
}

// ======================================================================
// av row 0 = mean of z -> written directly as bf16 hi/lo
// ======================================================================
__global__ __launch_bounds__(512) void av0_mean(const float* __restrict__ z,
                                                __nv_bfloat16* __restrict__ avhi,
                                                __nv_bfloat16* __restrict__ avlo)
{
    const int b = blockIdx.x;
    const float4* zb = (const float4*)(z + (size_t)b * LH);
    const int tid = threadIdx.x;
    const int hc = tid & 127;
    const int jg = tid >> 7;

    float4 acc = make_float4(0.f, 0.f, 0.f, 0.f);
#pragma unroll 8
    for (int j = jg * 512; j < (jg + 1) * 512; j++) {
        float4 v = zb[(long long)j * 128 + hc];
        acc.x += v.x; acc.y += v.y; acc.z += v.z; acc.w += v.w;
    }
    __shared__ float4 part[4][128];
    part[jg][hc] = acc;
    __syncthreads();
    if (tid < 128) {
        float4 s = part[0][tid];
        float4 p1 = part[1][tid], p2 = part[2][tid], p3 = part[3][tid];
        float vv[4];
        vv[0] = (s.x + p1.x + p2.x + p3.x) * (1.f / L_);
        vv[1] = (s.y + p1.y + p2.y + p3.y) * (1.f / L_);
        vv[2] = (s.z + p1.z + p2.z + p3.z) * (1.f / L_);
        vv[3] = (s.w + p1.w + p2.w + p3.w) * (1.f / L_);
        __nv_bfloat16* ah = avhi + (size_t)b * LH + tid * 4;
        __nv_bfloat16* al = avlo + (size_t)b * LH + tid * 4;
#pragma unroll
        for (int q = 0; q < 4; q++) {
            __nv_bfloat16 h = __float2bfloat16(vv[q]);
            ah[q] = h;
            al[q] = __float2bfloat16(vv[q] - __bfloat162float(h));
        }
    }
}

// ======================================================================
// split fp32 -> (bf16 hi, bf16 lo)
// ======================================================================
__global__ __launch_bounds__(1024) void split_bf16(
    const float* __restrict__ x, __nv_bfloat16* __restrict__ hi,
    __nv_bfloat16* __restrict__ lo, int n)
{
    int i = blockIdx.x * 1024 + threadIdx.x;
    if (i < n) {
        float v = x[i];
        __nv_bfloat16 h = __float2bfloat16(v);
        hi[i] = h;
        lo[i] = __float2bfloat16(v - __bfloat162float(h));
    }
}

// ======================================================================
extern "C" void kernel_launch(void* const* d_in, const int* in_sizes, int n_in,
                              void* d_out, int out_size)
{
    const int*   batch = (const int*)  d_in[0];
    const float* emb   = (const float*)d_in[1];
    const float* W_ih  = (const float*)d_in[2];
    const float* b_ih  = (const float*)d_in[3];
    const float* W_hh  = (const float*)d_in[4];
    const float* b_hh  = (const float*)d_in[5];
    const float* W_c   = (const float*)d_in[6];
    const float* b_c   = (const float*)d_in[7];
    const float* W_d   = (const float*)d_in[8];
    const float* b_d   = (const float*)d_in[9];
    float* out = (float*)d_out;

    float *embproj, *zbuf, *Pbuf, *decbuf;
    __nv_bfloat16 *phi, *plo, *zthi, *ztlo;
    __nv_bfloat16 *dhi, *dlo, *wdhi, *wdlo, *zhi, *zlo, *avhi, *avlo;
    __nv_bfloat16 *ehi, *elo, *wihhi, *wihlo, *wchi, *wclo;
    cudaGetSymbolAddress((void**)&embproj, g_embproj);
    cudaGetSymbolAddress((void**)&zbuf,    g_z);
    cudaGetSymbolAddress((void**)&Pbuf,    g_P);
    cudaGetSymbolAddress((void**)&decbuf,  g_dec);
    cudaGetSymbolAddress((void**)&phi,     g_P_hi);
    cudaGetSymbolAddress((void**)&plo,     g_P_lo);
    cudaGetSymbolAddress((void**)&zthi,    g_zT_hi);
    cudaGetSymbolAddress((void**)&ztlo,    g_zT_lo);
    cudaGetSymbolAddress((void**)&dhi,     g_dec_hi);
    cudaGetSymbolAddress((void**)&dlo,     g_dec_lo);
    cudaGetSymbolAddress((void**)&wdhi,    g_wd_hi);
    cudaGetSymbolAddress((void**)&wdlo,    g_wd_lo);
    cudaGetSymbolAddress((void**)&zhi,     g_z_hi);
    cudaGetSymbolAddress((void**)&zlo,     g_z_lo);
    cudaGetSymbolAddress((void**)&avhi,    g_av_hi);
    cudaGetSymbolAddress((void**)&avlo,    g_av_lo);
    cudaGetSymbolAddress((void**)&ehi,     g_emb_hi);
    cudaGetSymbolAddress((void**)&elo,     g_emb_lo);
    cudaGetSymbolAddress((void**)&wihhi,   g_wih_hi);
    cudaGetSymbolAddress((void**)&wihlo,   g_wih_lo);
    cudaGetSymbolAddress((void**)&wchi,    g_wc_hi);
    cudaGetSymbolAddress((void**)&wclo,    g_wc_lo);

    cudaFuncSetAttribute(hgemm_nt, cudaFuncAttributeMaxDynamicSharedMemorySize, HG_SMEM);

    static cudaStream_t s2 = nullptr;
    static cudaEvent_t evZ = nullptr, evT = nullptr, evDecZ = nullptr;
    if (!s2) {
        cudaStreamCreateWithFlags(&s2, cudaStreamNonBlocking);
        cudaEventCreateWithFlags(&evZ,    cudaEventDisableTiming);
        cudaEventCreateWithFlags(&evT,    cudaEventDisableTiming);
        cudaEventCreateWithFlags(&evDecZ, cudaEventDisableTiming);
    }

    const int ML = B_ * L_;   // 16384

    // ---- side stream: W_c / W_d splits overlap with the main head ----
    split_bf16<<<(H_ * 2 * H_ + 1023) / 1024, 1024, 0, s2>>>(W_c, wchi, wclo, H_ * 2 * H_);
    split_bf16<<<(V_ * H_ + 1023) / 1024, 1024, 0, s2>>>(W_d, wdhi, wdlo, V_ * H_);

    // ---- main: emb/W_ih splits -> embproj -> RNN ----
    split_bf16<<<(V_ * H_ + 1023) / 1024, 1024>>>(emb, ehi, elo, V_ * H_);
    split_bf16<<<(H_ * H_ + 1023) / 1024, 1024>>>(W_ih, wihhi, wihlo, H_ * H_);

    hgemm_nt<<<dim3(4, 79, 1), 256, HG_SMEM>>>(
        ehi, elo, H_, 0, wihhi, wihlo, H_, 0,
        embproj, nullptr, nullptr, H_, 0, V_, H_, H_, b_ih, 0);

    rnn_kernel<<<64, 512>>>(batch, embproj, W_hh, b_hh, zbuf, zhi, zlo);
    cudaEventRecord(evZ, 0);

    // ---- side branch: transpose + z-part decoder GEMM (with bias) ----
    cudaStreamWaitEvent(s2, evZ, 0);
    transpose_split<<<dim3(L_ / 32, H_ / 32, B_), 256, 0, s2>>>(zbuf, zthi, ztlo);
    cudaEventRecord(evT, s2);
    hgemm_nt<<<dim3(4, 128, 1), 256, HG_SMEM, s2>>>(
        zhi, zlo, H_, 0, wchi + H_, wclo + H_, 2 * H_, 0,
        decbuf, nullptr, nullptr, H_, 0, ML, H_, H_, b_c, 0);
    cudaEventRecord(evDecZ, s2);

    // ---- main branch: attention chain ----
    hgemm_nt<<<dim3(16, 16, B_), 256, HG_SMEM>>>(
        zhi, zlo, H_, LH, zhi, zlo, H_, LH,
        Pbuf, nullptr, nullptr, L_, LL, L_, L_, H_, nullptr, 2);

    softmax_rows<<<dim3(L_, B_), 256>>>(Pbuf, phi, plo);

    // av = P @ z^T  (causal K-limit, fused bf16-split output)
    cudaStreamWaitEvent(0, evT, 0);
    hgemm_nt<<<dim3(4, 16, B_), 256, HG_SMEM>>>(
        phi, plo, L_, LL, zthi, ztlo, L_, (long long)H_ * L_,
        nullptr, avhi, avlo, H_, LH, L_, H_, L_, nullptr, 4 | 8);

    // fix row 0: uniform attention -> mean of z, written as hi/lo
    av0_mean<<<B_, 512>>>(zbuf, avhi, avlo);

    // dec += av @ W_c[:, :H]^T  (accumulate fp32 dec, emit bf16 hi/lo)
    cudaStreamWaitEvent(0, evDecZ, 0);
    hgemm_nt<<<dim3(4, 128, 1), 256, HG_SMEM>>>(
        avhi, avlo, H_, 0, wchi, wclo, 2 * H_, 0,
        decbuf, dhi, dlo, H_, 0, ML, H_, H_, nullptr, 1 | 8);

    // logits = dec @ W_d^T + b_d
    hgemm_nt<<<dim3(79, 128, 1), 256, HG_SMEM>>>(
        dhi, dlo, H_, 0, wdhi, wdlo, H_, 0,
        out, nullptr, nullptr, V_, 0, ML, V_, H_, b_d, 0);
}